// round 5
// baseline (speedup 1.0000x reference)
#include <cuda_runtime.h>
#include <cstdint>
#include <math.h>

// ---------------- problem constants ----------------
#define B_   16
#define S_   2048
#define DIN  512
#define DH   1024
#define DH2  512
#define DOUT 10
#define M_   (B_ * S_)   // 32768

// ---------------- scratch (device globals; allocation-free) ----------------
__device__ float g_h1 [(size_t)M_ * (2 * DIN)];
__device__ float g_h  [(size_t)M_ * DH];
__device__ float g_attn[(size_t)B_ * S_ * S_];
__device__ float g_ctx[(size_t)M_ * DH];
__device__ float g_o  [(size_t)M_ * DH2];
__device__ float g_inr[(size_t)M_ * DIN];
__device__ float g_ht [(size_t)M_ * DH];           // per-batch H^T [DH][S]
__device__ float g_w1t[(size_t)(2 * DIN) * DIN];   // [N,K]
__device__ float g_w2t[(size_t)DH * (2 * DIN)];
__device__ float g_w3t[(size_t)DH2 * DH];

// ---------------- helpers ----------------
__device__ __forceinline__ uint32_t f2tf32(float f) {
    uint32_t u;
    asm("cvt.rna.tf32.f32 %0, %1;" : "=r"(u) : "f"(f));
    return u;
}
__device__ __forceinline__ float round_tf32(float f) {
    return __uint_as_float(f2tf32(f));
}
__device__ __forceinline__ uint32_t smem_u32(const void* p) {
    uint32_t a;
    asm("{ .reg .u64 t; cvta.to.shared.u64 t, %1; cvt.u32.u64 %0, t; }" : "=r"(a) : "l"(p));
    return a;
}
__device__ __forceinline__ void cp16(uint32_t dst, const void* src) {
    asm volatile("cp.async.cg.shared.global [%0], [%1], 16;" :: "r"(dst), "l"(src));
}
#define CP_COMMIT() asm volatile("cp.async.commit_group;" ::: "memory")
#define CP_WAIT(N)  asm volatile("cp.async.wait_group %0;" :: "n"(N) : "memory")

__device__ __forceinline__ void ldsm_x4(uint32_t* r, uint32_t addr) {
    asm volatile("ldmatrix.sync.aligned.m8n8.x4.shared.b16 {%0,%1,%2,%3}, [%4];"
        : "=r"(r[0]), "=r"(r[1]), "=r"(r[2]), "=r"(r[3]) : "r"(addr));
}
__device__ __forceinline__ void mma_tf32(float* d, const uint32_t* a, const uint32_t* b) {
    asm volatile(
        "mma.sync.aligned.m16n8k8.row.col.f32.tf32.tf32.f32 "
        "{%0,%1,%2,%3}, {%4,%5,%6,%7}, {%8,%9}, {%0,%1,%2,%3};"
        : "+f"(d[0]), "+f"(d[1]), "+f"(d[2]), "+f"(d[3])
        : "r"(a[0]), "r"(a[1]), "r"(a[2]), "r"(a[3]), "r"(b[0]), "r"(b[1]));
}

// ---------------- GEMM geometry ----------------
// CTA 128x128, BK=16, 4-stage cp.async, 8 warps = 2(m) x 4(n), warp 64x32.
// Both operands SMEM layout: [128 rows][16 k + 4 pad] fp32 (pitch 80 B).
#define APITCH 20
#define ABYTES 10240
#define SBYTES 20480
#define STAGES 4
#define GEMM_SMEM (STAGES * SBYTES)   // 81920

// ---------------------------------------------------------------------------
// NT tf32 GEMM: C[M,N] = act(A[M,K] @ B[N,K]^T + bias). Batched via blockIdx.z.
// ---------------------------------------------------------------------------
template<bool RELU, bool HAS_BIAS, bool CSKIP, bool KCUT, bool ROUND>
__global__ void __launch_bounds__(256, 2)
gemm_mma(const float* __restrict__ A, const float* __restrict__ Bsrc,
         const float* __restrict__ bias, float* __restrict__ C,
         int lda, int ldb, int ldc, int K,
         size_t strA, size_t strB, size_t strC)
{
    const int m0 = blockIdx.y * 128;
    const int n0 = blockIdx.x * 128;
    if (CSKIP && n0 > m0 + 127) return;

    A    += (size_t)blockIdx.z * strA;
    Bsrc += (size_t)blockIdx.z * strB;
    C    += (size_t)blockIdx.z * strC;

    const int Keff = KCUT ? ((m0 + 128) < K ? (m0 + 128) : K) : K;
    const int NC = Keff >> 4;

    extern __shared__ char smem[];
    const uint32_t sb = smem_u32(smem);

    const int tid  = threadIdx.x;
    const int lane = tid & 31;
    const int wid  = tid >> 5;
    const int wm   = wid & 1;
    const int wn   = wid >> 1;
    const int fc   = lane & 3;
    const int fr   = lane >> 2;

    const int a_row = tid >> 2, a_q = tid & 3;

    #define FILL(stage, c) do {                                                    \
        const uint32_t _ab = sb + (stage) * SBYTES;                                 \
        const uint32_t _bb = _ab + ABYTES;                                          \
        const int _k = (c) * 16;                                                    \
        _Pragma("unroll")                                                           \
        for (int hh = 0; hh < 2; hh++) {                                            \
            const int r = a_row + hh * 64;                                          \
            cp16(_ab + (uint32_t)(r * APITCH + a_q * 4) * 4,                        \
                 A + (size_t)(m0 + r) * lda + _k + a_q * 4);                        \
            cp16(_bb + (uint32_t)(r * APITCH + a_q * 4) * 4,                        \
                 Bsrc + (size_t)(n0 + r) * ldb + _k + a_q * 4);                     \
        }                                                                           \
    } while (0)

    float acc[4][4][4];
    #pragma unroll
    for (int i = 0; i < 4; i++)
        #pragma unroll
        for (int j = 0; j < 4; j++)
            #pragma unroll
            for (int r = 0; r < 4; r++) acc[i][j][r] = 0.0f;

    #pragma unroll
    for (int s = 0; s < STAGES - 1; s++) {
        if (s < NC) FILL(s, s);
        CP_COMMIT();
    }

    // ldmatrix per-lane offsets (bytes, within a stage's operand tile)
    //  A .x4: lanes 0-15 rows 0..15 chunk0; lanes 16-31 rows 0..15 chunk1
    const uint32_t aoff = (uint32_t)((lane & 15) * 80 + (lane >> 4) * 16);
    //  B .x4 (two n8 frags): g=lane>>3: row_off=(g>>1)*8+(lane&7), chunk=g&1
    const uint32_t boff = (uint32_t)((((lane >> 4) & 1) * 8 + (lane & 7)) * 80
                                     + ((lane >> 3) & 1) * 16);

    for (int c = 0; c < NC; ++c) {
        if (c + STAGES - 1 < NC) FILL((c + STAGES - 1) % STAGES, c + STAGES - 1);
        CP_COMMIT();
        CP_WAIT(STAGES - 1);
        __syncthreads();

        const uint32_t stb   = sb + (c % STAGES) * SBYTES;
        const uint32_t aBase = stb + (uint32_t)(wm * 64) * 80 + aoff;
        const uint32_t bBase = stb + ABYTES + (uint32_t)(wn * 32) * 80 + boff;

        #pragma unroll
        for (int s = 0; s < 2; ++s) {
            uint32_t bf[4][2];
            {
                uint32_t t[4];
                ldsm_x4(t, bBase + s * 32);
                bf[0][0] = t[0]; bf[0][1] = t[1]; bf[1][0] = t[2]; bf[1][1] = t[3];
                ldsm_x4(t, bBase + 16 * 80 + s * 32);
                bf[2][0] = t[0]; bf[2][1] = t[1]; bf[3][0] = t[2]; bf[3][1] = t[3];
            }
            #pragma unroll
            for (int mt = 0; mt < 4; ++mt) {
                uint32_t af[4];
                ldsm_x4(af, aBase + (uint32_t)(mt * 16) * 80 + s * 32);
                #pragma unroll
                for (int nt = 0; nt < 4; ++nt)
                    mma_tf32(acc[mt][nt], af, bf[nt]);
            }
        }
        __syncthreads();
    }

    // ---- epilogue ----
    #pragma unroll
    for (int mt = 0; mt < 4; ++mt) {
        #pragma unroll
        for (int nt = 0; nt < 4; ++nt) {
            const int row = m0 + wm * 64 + mt * 16 + fr;
            const int col = n0 + wn * 32 + nt * 8 + 2 * fc;
            float b0 = 0.f, b1 = 0.f;
            if (HAS_BIAS) { b0 = bias[col]; b1 = bias[col + 1]; }
            float2 v0, v1;
            v0.x = acc[mt][nt][0] + b0;  v0.y = acc[mt][nt][1] + b1;
            v1.x = acc[mt][nt][2] + b0;  v1.y = acc[mt][nt][3] + b1;
            if (RELU) {
                v0.x = fmaxf(v0.x, 0.f); v0.y = fmaxf(v0.y, 0.f);
                v1.x = fmaxf(v1.x, 0.f); v1.y = fmaxf(v1.y, 0.f);
            }
            if (ROUND) {
                v0.x = round_tf32(v0.x); v0.y = round_tf32(v0.y);
                v1.x = round_tf32(v1.x); v1.y = round_tf32(v1.y);
            }
            *(float2*)(C + (size_t)row * ldc + col) = v0;
            *(float2*)(C + (size_t)(row + 8) * ldc + col) = v1;
        }
    }
    #undef FILL
}

// ---------------------------------------------------------------------------
// Elementwise tf32 rounding.
// ---------------------------------------------------------------------------
__global__ void round_k(const float* __restrict__ in, float* __restrict__ out, int n4)
{
    int i = blockIdx.x * 256 + threadIdx.x;
    if (i < n4) {
        float4 v = ((const float4*)in)[i];
        v.x = round_tf32(v.x); v.y = round_tf32(v.y);
        v.z = round_tf32(v.z); v.w = round_tf32(v.w);
        ((float4*)out)[i] = v;
    }
}

// ---------------------------------------------------------------------------
// Transpose + tf32 round: out[C,R] = round(in[R,C]^T). Batched via blockIdx.z.
// ---------------------------------------------------------------------------
__global__ void trp_round(const float* __restrict__ in, float* __restrict__ out,
                          int R, int Cc)
{
    __shared__ float t[32][33];
    const size_t boff = (size_t)blockIdx.z * R * Cc;
    in += boff; out += boff;
    const int c0 = blockIdx.x * 32, r0 = blockIdx.y * 32;
    const int x = threadIdx.x, y = threadIdx.y;   // 32 x 8
    #pragma unroll
    for (int i = 0; i < 32; i += 8)
        t[y + i][x] = in[(size_t)(r0 + y + i) * Cc + c0 + x];
    __syncthreads();
    #pragma unroll
    for (int i = 0; i < 32; i += 8)
        out[(size_t)(c0 + y + i) * R + r0 + x] = round_tf32(t[x][y + i]);
}

// ---------------------------------------------------------------------------
// Single-pass causal softmax: 256 threads/row, row resident in registers.
// Zeros above the diagonal; tf32-rounds output (ctx GEMM A operand).
// ---------------------------------------------------------------------------
__global__ void softmax_causal(float* __restrict__ Sc)
{
    const int row = blockIdx.x, bb = blockIdx.y;
    float* r = Sc + (size_t)bb * S_ * S_ + (size_t)row * S_;
    const int n = row + 1;
    const int tid = threadIdx.x;
    const int lane = tid & 31, warp = tid >> 5;
    __shared__ float red[8];

    float v[8];
    #pragma unroll
    for (int q = 0; q < 8; q++) {
        const int j = tid + q * 256;
        v[q] = (j < n) ? r[j] : -INFINITY;
    }

    float m = v[0];
    #pragma unroll
    for (int q = 1; q < 8; q++) m = fmaxf(m, v[q]);
    #pragma unroll
    for (int s = 16; s > 0; s >>= 1) m = fmaxf(m, __shfl_xor_sync(~0u, m, s));
    if (lane == 0) red[warp] = m;
    __syncthreads();
    m = red[lane & 7];
    #pragma unroll
    for (int s = 4; s > 0; s >>= 1) m = fmaxf(m, __shfl_xor_sync(~0u, m, s));

    float sum = 0.0f;
    #pragma unroll
    for (int q = 0; q < 8; q++) {
        v[q] = (v[q] == -INFINITY) ? 0.0f : __expf(v[q] - m);
        sum += v[q];
    }
    #pragma unroll
    for (int s = 16; s > 0; s >>= 1) sum += __shfl_xor_sync(~0u, sum, s);
    __syncthreads();
    if (lane == 0) red[warp] = sum;
    __syncthreads();
    sum = red[lane & 7];
    #pragma unroll
    for (int s = 4; s > 0; s >>= 1) sum += __shfl_xor_sync(~0u, sum, s);
    const float inv = 1.0f / sum;

    #pragma unroll
    for (int q = 0; q < 8; q++)
        r[tid + q * 256] = round_tf32(v[q] * inv);
}

// ---------------------------------------------------------------------------
// Head: out = log_softmax(o @ W4 + b4). One warp per row.
// ---------------------------------------------------------------------------
__global__ void head_kernel(const float* __restrict__ O, const float* __restrict__ W4,
                            const float* __restrict__ b4, float* __restrict__ out)
{
    __shared__ float w[DH2 * DOUT];
    const int tid = threadIdx.x;
    for (int i = tid; i < DH2 * DOUT; i += 256) w[i] = W4[i];
    __syncthreads();

    const int warp = tid >> 5, lane = tid & 31;
    const int row = blockIdx.x * 8 + warp;
    const float* o = O + (size_t)row * DH2;

    float acc[DOUT];
    #pragma unroll
    for (int j = 0; j < DOUT; j++) acc[j] = 0.0f;
    for (int k = lane; k < DH2; k += 32) {
        float ov = o[k];
        const float* wk = &w[k * DOUT];
        #pragma unroll
        for (int j = 0; j < DOUT; j++) acc[j] = fmaf(ov, wk[j], acc[j]);
    }
    #pragma unroll
    for (int j = 0; j < DOUT; j++)
        #pragma unroll
        for (int s = 16; s > 0; s >>= 1)
            acc[j] += __shfl_xor_sync(0xffffffffu, acc[j], s);

    if (lane == 0) {
        float m = -INFINITY;
        #pragma unroll
        for (int j = 0; j < DOUT; j++) { acc[j] += b4[j]; m = fmaxf(m, acc[j]); }
        float sum = 0.0f;
        #pragma unroll
        for (int j = 0; j < DOUT; j++) sum += expf(acc[j] - m);
        float lse = m + logf(sum);
        #pragma unroll
        for (int j = 0; j < DOUT; j++)
            out[(size_t)row * DOUT + j] = acc[j] - lse;
    }
}

// ---------------------------------------------------------------------------
extern "C" void kernel_launch(void* const* d_in, const int* in_sizes, int n_in,
                              void* d_out, int out_size)
{
    const float* input = (const float*)d_in[0];
    const float* gamev = (const float*)d_in[1];
    const float* userv = (const float*)d_in[2];
    const float* W1 = (const float*)d_in[3];
    const float* b1 = (const float*)d_in[4];
    const float* W2 = (const float*)d_in[5];
    const float* b2 = (const float*)d_in[6];
    const float* W3 = (const float*)d_in[7];
    const float* b3 = (const float*)d_in[8];
    const float* W4 = (const float*)d_in[9];
    const float* b4 = (const float*)d_in[10];
    float* out = (float*)d_out;

    float *h1, *h, *attn, *ctx, *o, *inr, *ht, *w1t, *w2t, *w3t;
    cudaGetSymbolAddress((void**)&h1,   g_h1);
    cudaGetSymbolAddress((void**)&h,    g_h);
    cudaGetSymbolAddress((void**)&attn, g_attn);
    cudaGetSymbolAddress((void**)&ctx,  g_ctx);
    cudaGetSymbolAddress((void**)&o,    g_o);
    cudaGetSymbolAddress((void**)&inr,  g_inr);
    cudaGetSymbolAddress((void**)&ht,   g_ht);
    cudaGetSymbolAddress((void**)&w1t,  g_w1t);
    cudaGetSymbolAddress((void**)&w2t,  g_w2t);
    cudaGetSymbolAddress((void**)&w3t,  g_w3t);

    auto g_mlpR = gemm_mma<true,  true,  false, false, true >;
    auto g_sc   = gemm_mma<false, false, true,  false, false>;
    auto g_ctxk = gemm_mma<false, false, false, true,  true >;
    auto g_mlpN = gemm_mma<true,  true,  false, false, false>;
    cudaFuncSetAttribute(g_mlpR, cudaFuncAttributeMaxDynamicSharedMemorySize, GEMM_SMEM);
    cudaFuncSetAttribute(g_sc,   cudaFuncAttributeMaxDynamicSharedMemorySize, GEMM_SMEM);
    cudaFuncSetAttribute(g_ctxk, cudaFuncAttributeMaxDynamicSharedMemorySize, GEMM_SMEM);
    cudaFuncSetAttribute(g_mlpN, cudaFuncAttributeMaxDynamicSharedMemorySize, GEMM_SMEM);

    // tf32 pre-round / transpose of operands
    round_k<<<(M_ * DIN / 4 + 255) / 256, 256>>>(input, inr, M_ * DIN / 4);
    trp_round<<<dim3((2*DIN)/32, DIN/32, 1), dim3(32, 8)>>>(W1, w1t, DIN, 2*DIN);
    trp_round<<<dim3(DH/32, (2*DIN)/32, 1), dim3(32, 8)>>>(W2, w2t, 2*DIN, DH);
    trp_round<<<dim3(DH2/32, DH/32, 1),     dim3(32, 8)>>>(W3, w3t, DH, DH2);

    // 1) h1 = relu(inr @ W1 + b1)    M=32768 N=1024 K=512
    g_mlpR<<<dim3(8, 256, 1), 256, GEMM_SMEM>>>(inr, w1t, b1, h1,
        DIN, DIN, 2*DIN, DIN, 0, 0, 0);
    // 2) h = relu(h1 @ W2 + b2)      M=32768 N=1024 K=1024
    g_mlpR<<<dim3(8, 256, 1), 256, GEMM_SMEM>>>(h1, w2t, b2, h,
        2*DIN, 2*DIN, DH, 2*DIN, 0, 0, 0);
    // 3) scores = H @ H^T per batch (lower-tri tiles only)
    g_sc<<<dim3(16, 16, B_), 256, GEMM_SMEM>>>(h, h, nullptr, attn,
        DH, DH, S_, DH, (size_t)S_*DH, (size_t)S_*DH, (size_t)S_*S_);
    // 4) causal softmax (single-pass, rounds output)
    softmax_causal<<<dim3(S_, B_), 256>>>(attn);
    // 4b) H^T per batch for ctx GEMM B operand
    trp_round<<<dim3(DH/32, S_/32, B_), dim3(32, 8)>>>(h, ht, S_, DH);
    // 5) ctx = attn @ H per batch (K cutoff at m0+128)
    g_ctxk<<<dim3(8, 16, B_), 256, GEMM_SMEM>>>(attn, ht, nullptr, ctx,
        S_, S_, DH, S_, (size_t)S_*S_, (size_t)S_*DH, (size_t)S_*DH);
    // 6) o = relu(ctx @ W3 + b3)     M=32768 N=512 K=1024
    g_mlpN<<<dim3(4, 256, 1), 256, GEMM_SMEM>>>(ctx, w3t, b3, o,
        DH, DH, DH2, DH, 0, 0, 0);
    // 7) head + log_softmax
    head_kernel<<<M_ / 8, 256>>>(o, W4, b4, out);

    // 8) pass-through
    size_t off = (size_t)M_ * DOUT;
    cudaMemcpyAsync(out + off, gamev, (size_t)in_sizes[1] * sizeof(float),
                    cudaMemcpyDeviceToDevice);
    cudaMemcpyAsync(out + off + in_sizes[1], userv, (size_t)in_sizes[2] * sizeof(float),
                    cudaMemcpyDeviceToDevice);
}

// round 6
// speedup vs baseline: 1.7520x; 1.7520x over previous
#include <cuda_runtime.h>
#include <cuda_bf16.h>
#include <cstdint>
#include <math.h>

// ---------------- problem constants ----------------
#define B_   16
#define S_   2048
#define DIN  512
#define DH   1024
#define DH2  512
#define DOUT 10
#define M_   (B_ * S_)   // 32768

typedef __nv_bfloat16 bf16;

// ---------------- scratch (device globals; allocation-free) ----------------
__device__ bf16  g_inb [(size_t)M_ * DIN];
__device__ bf16  g_w1t [(size_t)(2 * DIN) * DIN];   // [N,K] bf16
__device__ bf16  g_w2t [(size_t)DH * (2 * DIN)];
__device__ bf16  g_w3t [(size_t)DH2 * DH];
__device__ bf16  g_h1b [(size_t)M_ * (2 * DIN)];
__device__ bf16  g_hb  [(size_t)M_ * DH];
__device__ bf16  g_htb [(size_t)M_ * DH];           // per-batch H^T [DH][S]
__device__ float g_attn[(size_t)B_ * S_ * S_];      // fp32 scores
__device__ bf16  g_attnb[(size_t)B_ * S_ * S_];     // bf16 attn weights
__device__ bf16  g_ctxb[(size_t)M_ * DH];
__device__ float g_o   [(size_t)M_ * DH2];

// ---------------- helpers ----------------
__device__ __forceinline__ uint32_t smem_u32(const void* p) {
    uint32_t a;
    asm("{ .reg .u64 t; cvta.to.shared.u64 t, %1; cvt.u32.u64 %0, t; }" : "=r"(a) : "l"(p));
    return a;
}
__device__ __forceinline__ void cp16(uint32_t dst, const void* src) {
    asm volatile("cp.async.cg.shared.global [%0], [%1], 16;" :: "r"(dst), "l"(src));
}
#define CP_COMMIT() asm volatile("cp.async.commit_group;" ::: "memory")
#define CP_WAIT(N)  asm volatile("cp.async.wait_group %0;" :: "n"(N) : "memory")

__device__ __forceinline__ void ldsm_x4(uint32_t* r, uint32_t addr) {
    asm volatile("ldmatrix.sync.aligned.m8n8.x4.shared.b16 {%0,%1,%2,%3}, [%4];"
        : "=r"(r[0]), "=r"(r[1]), "=r"(r[2]), "=r"(r[3]) : "r"(addr));
}
__device__ __forceinline__ void mma_bf16(float* d, const uint32_t* a, const uint32_t* b) {
    asm volatile(
        "mma.sync.aligned.m16n8k16.row.col.f32.bf16.bf16.f32 "
        "{%0,%1,%2,%3}, {%4,%5,%6,%7}, {%8,%9}, {%0,%1,%2,%3};"
        : "+f"(d[0]), "+f"(d[1]), "+f"(d[2]), "+f"(d[3])
        : "r"(a[0]), "r"(a[1]), "r"(a[2]), "r"(a[3]), "r"(b[0]), "r"(b[1]));
}

// ---------------- GEMM geometry ----------------
// CTA 128x128, BK=32 (bf16), 4-stage cp.async ring (1 sync/stage),
// 8 warps = 2(m) x 4(n), warp tile 64x32, m16n8k16 MMAs.
// Operand SMEM: [128 rows][32 k bf16 (64 B) + 16 B pad] -> pitch 80 B.
#define PB 80
#define ABYTES (128 * PB)          // 10240
#define SBYTES (2 * ABYTES)        // 20480
#define STAGES 4
#define GEMM_SMEM (STAGES * SBYTES)   // 81920

// ---------------------------------------------------------------------------
// NT bf16 GEMM: C[M,N] = act(A[M,K] @ B[N,K]^T + bias). Batched via blockIdx.z.
// ---------------------------------------------------------------------------
template<typename TO, bool RELU, bool HAS_BIAS, bool CSKIP, bool KCUT>
__global__ void __launch_bounds__(256, 2)
gemm_bf(const bf16* __restrict__ A, const bf16* __restrict__ Bsrc,
        const float* __restrict__ bias, TO* __restrict__ C,
        int lda, int ldb, int ldc, int K,
        size_t strA, size_t strB, size_t strC)
{
    const int m0 = blockIdx.y * 128;
    const int n0 = blockIdx.x * 128;
    if (CSKIP && n0 > m0 + 127) return;

    A    += (size_t)blockIdx.z * strA;
    Bsrc += (size_t)blockIdx.z * strB;
    C    += (size_t)blockIdx.z * strC;

    const int Keff = KCUT ? ((m0 + 128) < K ? (m0 + 128) : K) : K;
    const int NC = Keff >> 5;            // BK=32 stages

    extern __shared__ char smem[];
    const uint32_t sb = smem_u32(smem);

    const int tid  = threadIdx.x;
    const int lane = tid & 31;
    const int wid  = tid >> 5;
    const int wm   = wid & 1;
    const int wn   = wid >> 1;
    const int fc   = lane & 3;
    const int fr   = lane >> 2;

    // fill mapping: thread -> row (tid>>1), half (tid&1) -> 2 x 16B chunks
    const int f_row = tid >> 1;
    const int f_hf  = tid & 1;

    #define FILL(stage, c) do {                                                    \
        const uint32_t _ab = sb + (stage) * SBYTES;                                 \
        const uint32_t _bb = _ab + ABYTES;                                          \
        const int _k = (c) << 5;                                                    \
        _Pragma("unroll")                                                           \
        for (int j = 0; j < 2; j++) {                                               \
            const int ch = f_hf * 2 + j;                                            \
            cp16(_ab + (uint32_t)(f_row * PB + ch * 16),                            \
                 A + (size_t)(m0 + f_row) * lda + _k + ch * 8);                     \
            cp16(_bb + (uint32_t)(f_row * PB + ch * 16),                            \
                 Bsrc + (size_t)(n0 + f_row) * ldb + _k + ch * 8);                  \
        }                                                                           \
    } while (0)

    float acc[4][4][4];
    #pragma unroll
    for (int i = 0; i < 4; i++)
        #pragma unroll
        for (int j = 0; j < 4; j++)
            #pragma unroll
            for (int r = 0; r < 4; r++) acc[i][j][r] = 0.0f;

    #pragma unroll
    for (int s = 0; s < STAGES - 1; s++) {
        if (s < NC) FILL(s, s);
        CP_COMMIT();
    }

    // ldmatrix per-lane byte offsets within an operand tile
    const uint32_t aoff = (uint32_t)((lane & 15) * PB + (lane >> 4) * 16);
    const uint32_t boff = (uint32_t)((((lane >> 4) & 1) * 8 + (lane & 7)) * PB
                                     + ((lane >> 3) & 1) * 16);

    for (int c = 0; c < NC; ++c) {
        CP_WAIT(STAGES - 2);
        __syncthreads();                  // stage c ready; stage c-1 reads done
        if (c + STAGES - 1 < NC) FILL((c + STAGES - 1) & 3, c + STAGES - 1);
        CP_COMMIT();

        const uint32_t stb   = sb + (c & 3) * SBYTES;
        const uint32_t aBase = stb + (uint32_t)(wm * 64) * PB + aoff;
        const uint32_t bBase = stb + ABYTES + (uint32_t)(wn * 32) * PB + boff;

        #pragma unroll
        for (int s = 0; s < 2; ++s) {     // two k16 steps
            uint32_t bf[4][2];
            {
                uint32_t t[4];
                ldsm_x4(t, bBase + s * 32);
                bf[0][0] = t[0]; bf[0][1] = t[1]; bf[1][0] = t[2]; bf[1][1] = t[3];
                ldsm_x4(t, bBase + 16 * PB + s * 32);
                bf[2][0] = t[0]; bf[2][1] = t[1]; bf[3][0] = t[2]; bf[3][1] = t[3];
            }
            #pragma unroll
            for (int mt = 0; mt < 4; ++mt) {
                uint32_t af[4];
                ldsm_x4(af, aBase + (uint32_t)(mt * 16) * PB + s * 32);
                #pragma unroll
                for (int nt = 0; nt < 4; ++nt)
                    mma_bf16(acc[mt][nt], af, bf[nt]);
            }
        }
    }

    // ---- epilogue ----
    #pragma unroll
    for (int mt = 0; mt < 4; ++mt) {
        #pragma unroll
        for (int nt = 0; nt < 4; ++nt) {
            const int row = m0 + wm * 64 + mt * 16 + fr;
            const int col = n0 + wn * 32 + nt * 8 + 2 * fc;
            float b0 = 0.f, b1 = 0.f;
            if (HAS_BIAS) { b0 = bias[col]; b1 = bias[col + 1]; }
            float v00 = acc[mt][nt][0] + b0, v01 = acc[mt][nt][1] + b1;
            float v10 = acc[mt][nt][2] + b0, v11 = acc[mt][nt][3] + b1;
            if (RELU) {
                v00 = fmaxf(v00, 0.f); v01 = fmaxf(v01, 0.f);
                v10 = fmaxf(v10, 0.f); v11 = fmaxf(v11, 0.f);
            }
            if constexpr (sizeof(TO) == 4) {
                *(float2*)((float*)C + (size_t)row * ldc + col) = make_float2(v00, v01);
                *(float2*)((float*)C + (size_t)(row + 8) * ldc + col) = make_float2(v10, v11);
            } else {
                __nv_bfloat162 p0, p1;
                p0.x = __float2bfloat16_rn(v00); p0.y = __float2bfloat16_rn(v01);
                p1.x = __float2bfloat16_rn(v10); p1.y = __float2bfloat16_rn(v11);
                *(__nv_bfloat162*)((bf16*)C + (size_t)row * ldc + col) = p0;
                *(__nv_bfloat162*)((bf16*)C + (size_t)(row + 8) * ldc + col) = p1;
            }
        }
    }
    #undef FILL
}

// ---------------------------------------------------------------------------
// fp32 -> bf16 elementwise (rn).
// ---------------------------------------------------------------------------
__global__ void cvt_bf(const float* __restrict__ in, bf16* __restrict__ out, int n4)
{
    int i = blockIdx.x * 256 + threadIdx.x;
    if (i < n4) {
        float4 v = ((const float4*)in)[i];
        __nv_bfloat162 a, b;
        a.x = __float2bfloat16_rn(v.x); a.y = __float2bfloat16_rn(v.y);
        b.x = __float2bfloat16_rn(v.z); b.y = __float2bfloat16_rn(v.w);
        ((__nv_bfloat162*)out)[2 * i]     = a;
        ((__nv_bfloat162*)out)[2 * i + 1] = b;
    }
}

// ---------------------------------------------------------------------------
// Transpose fp32 [R,C] -> bf16 [C,R] (weights).
// ---------------------------------------------------------------------------
__global__ void trp_f2b(const float* __restrict__ in, bf16* __restrict__ out,
                        int R, int Cc)
{
    __shared__ float t[32][33];
    const int c0 = blockIdx.x * 32, r0 = blockIdx.y * 32;
    const int x = threadIdx.x, y = threadIdx.y;
    #pragma unroll
    for (int i = 0; i < 32; i += 8)
        t[y + i][x] = in[(size_t)(r0 + y + i) * Cc + c0 + x];
    __syncthreads();
    #pragma unroll
    for (int i = 0; i < 32; i += 8)
        out[(size_t)(c0 + y + i) * R + r0 + x] = __float2bfloat16_rn(t[x][y + i]);
}

// ---------------------------------------------------------------------------
// Transpose bf16 [R,C] -> bf16 [C,R], batched via blockIdx.z.
// ---------------------------------------------------------------------------
__global__ void trp_b2b(const bf16* __restrict__ in, bf16* __restrict__ out,
                        int R, int Cc)
{
    __shared__ bf16 t[32][33];
    const size_t boff = (size_t)blockIdx.z * R * Cc;
    in += boff; out += boff;
    const int c0 = blockIdx.x * 32, r0 = blockIdx.y * 32;
    const int x = threadIdx.x, y = threadIdx.y;
    #pragma unroll
    for (int i = 0; i < 32; i += 8)
        t[y + i][x] = in[(size_t)(r0 + y + i) * Cc + c0 + x];
    __syncthreads();
    #pragma unroll
    for (int i = 0; i < 32; i += 8)
        out[(size_t)(c0 + y + i) * R + r0 + x] = t[x][y + i];
}

// ---------------------------------------------------------------------------
// Single-pass causal softmax: fp32 scores in, bf16 weights out (zeros above diag).
// ---------------------------------------------------------------------------
__global__ void softmax_causal(const float* __restrict__ Sc, bf16* __restrict__ W)
{
    const int row = blockIdx.x, bb = blockIdx.y;
    const float* r = Sc + (size_t)bb * S_ * S_ + (size_t)row * S_;
    bf16* w = W + (size_t)bb * S_ * S_ + (size_t)row * S_;
    const int n = row + 1;
    const int tid = threadIdx.x;
    const int lane = tid & 31, warp = tid >> 5;
    __shared__ float red[8];

    float v[8];
    #pragma unroll
    for (int q = 0; q < 8; q++) {
        const int j = tid + q * 256;
        v[q] = (j < n) ? r[j] : -INFINITY;
    }

    float m = v[0];
    #pragma unroll
    for (int q = 1; q < 8; q++) m = fmaxf(m, v[q]);
    #pragma unroll
    for (int s = 16; s > 0; s >>= 1) m = fmaxf(m, __shfl_xor_sync(~0u, m, s));
    if (lane == 0) red[warp] = m;
    __syncthreads();
    m = red[lane & 7];
    #pragma unroll
    for (int s = 4; s > 0; s >>= 1) m = fmaxf(m, __shfl_xor_sync(~0u, m, s));

    float sum = 0.0f;
    #pragma unroll
    for (int q = 0; q < 8; q++) {
        v[q] = (v[q] == -INFINITY) ? 0.0f : __expf(v[q] - m);
        sum += v[q];
    }
    #pragma unroll
    for (int s = 16; s > 0; s >>= 1) sum += __shfl_xor_sync(~0u, sum, s);
    __syncthreads();
    if (lane == 0) red[warp] = sum;
    __syncthreads();
    sum = red[lane & 7];
    #pragma unroll
    for (int s = 4; s > 0; s >>= 1) sum += __shfl_xor_sync(~0u, sum, s);
    const float inv = 1.0f / sum;

    #pragma unroll
    for (int q = 0; q < 8; q++)
        w[tid + q * 256] = __float2bfloat16_rn(v[q] * inv);
}

// ---------------------------------------------------------------------------
// Head: out = log_softmax(o @ W4 + b4). One warp per row.
// ---------------------------------------------------------------------------
__global__ void head_kernel(const float* __restrict__ O, const float* __restrict__ W4,
                            const float* __restrict__ b4, float* __restrict__ out)
{
    __shared__ float w[DH2 * DOUT];
    const int tid = threadIdx.x;
    for (int i = tid; i < DH2 * DOUT; i += 256) w[i] = W4[i];
    __syncthreads();

    const int warp = tid >> 5, lane = tid & 31;
    const int row = blockIdx.x * 8 + warp;
    const float* o = O + (size_t)row * DH2;

    float acc[DOUT];
    #pragma unroll
    for (int j = 0; j < DOUT; j++) acc[j] = 0.0f;
    for (int k = lane; k < DH2; k += 32) {
        float ov = o[k];
        const float* wk = &w[k * DOUT];
        #pragma unroll
        for (int j = 0; j < DOUT; j++) acc[j] = fmaf(ov, wk[j], acc[j]);
    }
    #pragma unroll
    for (int j = 0; j < DOUT; j++)
        #pragma unroll
        for (int s = 16; s > 0; s >>= 1)
            acc[j] += __shfl_xor_sync(0xffffffffu, acc[j], s);

    if (lane == 0) {
        float m = -INFINITY;
        #pragma unroll
        for (int j = 0; j < DOUT; j++) { acc[j] += b4[j]; m = fmaxf(m, acc[j]); }
        float sum = 0.0f;
        #pragma unroll
        for (int j = 0; j < DOUT; j++) sum += expf(acc[j] - m);
        float lse = m + logf(sum);
        #pragma unroll
        for (int j = 0; j < DOUT; j++)
            out[(size_t)row * DOUT + j] = acc[j] - lse;
    }
}

// ---------------------------------------------------------------------------
extern "C" void kernel_launch(void* const* d_in, const int* in_sizes, int n_in,
                              void* d_out, int out_size)
{
    const float* input = (const float*)d_in[0];
    const float* gamev = (const float*)d_in[1];
    const float* userv = (const float*)d_in[2];
    const float* W1 = (const float*)d_in[3];
    const float* b1 = (const float*)d_in[4];
    const float* W2 = (const float*)d_in[5];
    const float* b2 = (const float*)d_in[6];
    const float* W3 = (const float*)d_in[7];
    const float* b3 = (const float*)d_in[8];
    const float* W4 = (const float*)d_in[9];
    const float* b4 = (const float*)d_in[10];
    float* out = (float*)d_out;

    bf16 *inb, *w1t, *w2t, *w3t, *h1b, *hb, *htb, *attnb, *ctxb;
    float *attn, *o;
    cudaGetSymbolAddress((void**)&inb,   g_inb);
    cudaGetSymbolAddress((void**)&w1t,   g_w1t);
    cudaGetSymbolAddress((void**)&w2t,   g_w2t);
    cudaGetSymbolAddress((void**)&w3t,   g_w3t);
    cudaGetSymbolAddress((void**)&h1b,   g_h1b);
    cudaGetSymbolAddress((void**)&hb,    g_hb);
    cudaGetSymbolAddress((void**)&htb,   g_htb);
    cudaGetSymbolAddress((void**)&attn,  g_attn);
    cudaGetSymbolAddress((void**)&attnb, g_attnb);
    cudaGetSymbolAddress((void**)&ctxb,  g_ctxb);
    cudaGetSymbolAddress((void**)&o,     g_o);

    auto g_mlpB = gemm_bf<bf16,  true,  true,  false, false>;  // relu+bias -> bf16
    auto g_sc   = gemm_bf<float, false, false, true,  false>;  // scores -> fp32
    auto g_ctxk = gemm_bf<bf16,  false, false, false, true >;  // ctx -> bf16
    auto g_mlpF = gemm_bf<float, true,  true,  false, false>;  // final mlp -> fp32
    cudaFuncSetAttribute(g_mlpB, cudaFuncAttributeMaxDynamicSharedMemorySize, GEMM_SMEM);
    cudaFuncSetAttribute(g_sc,   cudaFuncAttributeMaxDynamicSharedMemorySize, GEMM_SMEM);
    cudaFuncSetAttribute(g_ctxk, cudaFuncAttributeMaxDynamicSharedMemorySize, GEMM_SMEM);
    cudaFuncSetAttribute(g_mlpF, cudaFuncAttributeMaxDynamicSharedMemorySize, GEMM_SMEM);

    // operand conversions
    cvt_bf<<<(M_ * DIN / 4 + 255) / 256, 256>>>(input, inb, M_ * DIN / 4);
    trp_f2b<<<dim3((2*DIN)/32, DIN/32), dim3(32, 8)>>>(W1, w1t, DIN, 2*DIN);
    trp_f2b<<<dim3(DH/32, (2*DIN)/32),  dim3(32, 8)>>>(W2, w2t, 2*DIN, DH);
    trp_f2b<<<dim3(DH2/32, DH/32),      dim3(32, 8)>>>(W3, w3t, DH, DH2);

    // 1) h1 = relu(in @ W1 + b1)    M=32768 N=1024 K=512
    g_mlpB<<<dim3(8, 256, 1), 256, GEMM_SMEM>>>(inb, w1t, b1, h1b,
        DIN, DIN, 2*DIN, DIN, 0, 0, 0);
    // 2) h = relu(h1 @ W2 + b2)     M=32768 N=1024 K=1024
    g_mlpB<<<dim3(8, 256, 1), 256, GEMM_SMEM>>>(h1b, w2t, b2, hb,
        2*DIN, 2*DIN, DH, 2*DIN, 0, 0, 0);
    // 3) scores = H @ H^T per batch (lower-tri tiles), fp32 out
    g_sc<<<dim3(16, 16, B_), 256, GEMM_SMEM>>>(hb, hb, nullptr, attn,
        DH, DH, S_, DH, (size_t)S_*DH, (size_t)S_*DH, (size_t)S_*S_);
    // 4) causal softmax fp32 -> bf16 weights
    softmax_causal<<<dim3(S_, B_), 256>>>(attn, attnb);
    // 4b) H^T per batch
    trp_b2b<<<dim3(DH/32, S_/32, B_), dim3(32, 8)>>>(hb, htb, S_, DH);
    // 5) ctx = attn @ H per batch (K cutoff)
    g_ctxk<<<dim3(8, 16, B_), 256, GEMM_SMEM>>>(attnb, htb, nullptr, ctxb,
        S_, S_, DH, S_, (size_t)S_*S_, (size_t)S_*DH, (size_t)S_*DH);
    // 6) o = relu(ctx @ W3 + b3)    M=32768 N=512 K=1024 -> fp32
    g_mlpF<<<dim3(4, 256, 1), 256, GEMM_SMEM>>>(ctxb, w3t, b3, o,
        DH, DH, DH2, DH, 0, 0, 0);
    // 7) head + log_softmax
    head_kernel<<<M_ / 8, 256>>>(o, W4, b4, out);

    // 8) pass-through
    size_t off = (size_t)M_ * DOUT;
    cudaMemcpyAsync(out + off, gamev, (size_t)in_sizes[1] * sizeof(float),
                    cudaMemcpyDeviceToDevice);
    cudaMemcpyAsync(out + off + in_sizes[1], userv, (size_t)in_sizes[2] * sizeof(float),
                    cudaMemcpyDeviceToDevice);
}

// round 7
// speedup vs baseline: 1.7730x; 1.0120x over previous
#include <cuda_runtime.h>
#include <cuda_bf16.h>
#include <cstdint>
#include <math.h>

// ---------------- problem constants ----------------
#define B_   16
#define S_   2048
#define DIN  512
#define DH   1024
#define DH2  512
#define DOUT 10
#define M_   (B_ * S_)   // 32768

typedef __nv_bfloat16 bf16;

// ---------------- scratch (device globals; allocation-free) ----------------
__device__ bf16  g_inb [(size_t)M_ * DIN];
__device__ bf16  g_w1t [(size_t)(2 * DIN) * DIN];   // [N,K] bf16
__device__ bf16  g_w2t [(size_t)DH * (2 * DIN)];
__device__ bf16  g_w3t [(size_t)DH2 * DH];
__device__ bf16  g_h1b [(size_t)M_ * (2 * DIN)];
__device__ bf16  g_hb  [(size_t)M_ * DH];
__device__ float g_attn[(size_t)B_ * S_ * S_];      // fp32 scores
__device__ bf16  g_attnb[(size_t)B_ * S_ * S_];     // bf16 attn weights
__device__ bf16  g_ctxb[(size_t)M_ * DH];
__device__ float g_o   [(size_t)M_ * DH2];

// ---------------- helpers ----------------
__device__ __forceinline__ uint32_t smem_u32(const void* p) {
    uint32_t a;
    asm("{ .reg .u64 t; cvta.to.shared.u64 t, %1; cvt.u32.u64 %0, t; }" : "=r"(a) : "l"(p));
    return a;
}
__device__ __forceinline__ void cp16(uint32_t dst, const void* src) {
    asm volatile("cp.async.cg.shared.global [%0], [%1], 16;" :: "r"(dst), "l"(src));
}
#define CP_COMMIT() asm volatile("cp.async.commit_group;" ::: "memory")
#define CP_WAIT(N)  asm volatile("cp.async.wait_group %0;" :: "n"(N) : "memory")

__device__ __forceinline__ void ldsm_x4(uint32_t* r, uint32_t addr) {
    asm volatile("ldmatrix.sync.aligned.m8n8.x4.shared.b16 {%0,%1,%2,%3}, [%4];"
        : "=r"(r[0]), "=r"(r[1]), "=r"(r[2]), "=r"(r[3]) : "r"(addr));
}
__device__ __forceinline__ void ldsm_x4_t(uint32_t* r, uint32_t addr) {
    asm volatile("ldmatrix.sync.aligned.m8n8.x4.trans.shared.b16 {%0,%1,%2,%3}, [%4];"
        : "=r"(r[0]), "=r"(r[1]), "=r"(r[2]), "=r"(r[3]) : "r"(addr));
}
__device__ __forceinline__ void mma_bf16(float* d, const uint32_t* a, const uint32_t* b) {
    asm volatile(
        "mma.sync.aligned.m16n8k16.row.col.f32.bf16.bf16.f32 "
        "{%0,%1,%2,%3}, {%4,%5,%6,%7}, {%8,%9}, {%0,%1,%2,%3};"
        : "+f"(d[0]), "+f"(d[1]), "+f"(d[2]), "+f"(d[3])
        : "r"(a[0]), "r"(a[1]), "r"(a[2]), "r"(a[3]), "r"(b[0]), "r"(b[1]));
}

// ---------------- GEMM geometry ----------------
// CTA 128x128, BK=32 bf16, 4-stage cp.async ring, 8 warps = 2(m) x 4(n),
// warp tile 64x32, m16n8k16.
// A smem: [128 rows][64 B k + 16 B pad] pitch 80.
// B smem NT: same as A. B smem NN: [32 k-rows][256 B n + 16 B pad] pitch 272.
#define PA 80
#define PBN 272
#define ABYTES (128 * PA)          // 10240
#define STAGES 4

template<typename TO, bool RELU, bool HAS_BIAS, bool BNN, bool CSKIP, bool KCUT, bool REVY>
__global__ void __launch_bounds__(256, 2)
gemm_bf(const bf16* __restrict__ A, const bf16* __restrict__ Bsrc,
        const float* __restrict__ bias, TO* __restrict__ C,
        int lda, int ldb, int ldc, int K,
        size_t strA, size_t strB, size_t strC)
{
    constexpr int BBYTES = BNN ? (32 * PBN) : ABYTES;
    constexpr int SB     = ABYTES + BBYTES;

    const int by = REVY ? (gridDim.y - 1 - blockIdx.y) : blockIdx.y;
    const int m0 = by * 128;
    const int n0 = blockIdx.x * 128;
    if (CSKIP && n0 > m0 + 127) return;

    A    += (size_t)blockIdx.z * strA;
    Bsrc += (size_t)blockIdx.z * strB;
    C    += (size_t)blockIdx.z * strC;

    const int Keff = KCUT ? ((m0 + 128) < K ? (m0 + 128) : K) : K;
    const int NC = Keff >> 5;

    extern __shared__ char smem[];
    const uint32_t sb = smem_u32(smem);

    const int tid  = threadIdx.x;
    const int lane = tid & 31;
    const int wid  = tid >> 5;
    const int wm   = wid & 1;
    const int wn   = wid >> 1;
    const int fc   = lane & 3;
    const int fr   = lane >> 2;

    // fill mappings
    const int f_row = tid >> 1, f_hf = tid & 1;        // A (and NT B)
    const int bn_r  = tid >> 4, bn_c = tid & 15;       // NN B

    #define FILL(stage, c) do {                                                    \
        const uint32_t _ab = sb + (stage) * SB;                                     \
        const uint32_t _bb = _ab + ABYTES;                                          \
        const int _k = (c) << 5;                                                    \
        _Pragma("unroll")                                                           \
        for (int j = 0; j < 2; j++) {                                               \
            const int ch = f_hf * 2 + j;                                            \
            cp16(_ab + (uint32_t)(f_row * PA + ch * 16),                            \
                 A + (size_t)(m0 + f_row) * lda + _k + ch * 8);                     \
        }                                                                           \
        if (BNN) {                                                                  \
            cp16(_bb + (uint32_t)(bn_r * PBN + bn_c * 16),                          \
                 Bsrc + (size_t)(_k + bn_r) * ldb + n0 + bn_c * 8);                 \
            cp16(_bb + (uint32_t)((bn_r + 16) * PBN + bn_c * 16),                   \
                 Bsrc + (size_t)(_k + bn_r + 16) * ldb + n0 + bn_c * 8);            \
        } else {                                                                    \
            _Pragma("unroll")                                                       \
            for (int j = 0; j < 2; j++) {                                           \
                const int ch = f_hf * 2 + j;                                        \
                cp16(_bb + (uint32_t)(f_row * PA + ch * 16),                        \
                     Bsrc + (size_t)(n0 + f_row) * ldb + _k + ch * 8);              \
            }                                                                       \
        }                                                                           \
    } while (0)

    float acc[4][4][4];
    #pragma unroll
    for (int i = 0; i < 4; i++)
        #pragma unroll
        for (int j = 0; j < 4; j++)
            #pragma unroll
            for (int r = 0; r < 4; r++) acc[i][j][r] = 0.0f;

    #pragma unroll
    for (int s = 0; s < STAGES - 1; s++) {
        if (s < NC) FILL(s, s);
        CP_COMMIT();
    }

    // ldmatrix per-lane byte offsets
    const uint32_t aoff   = (uint32_t)((lane & 15) * PA + (lane >> 4) * 16);
    const uint32_t boffNT = (uint32_t)((((lane >> 4) & 1) * 8 + (lane & 7)) * PA
                                       + ((lane >> 3) & 1) * 16);
    const uint32_t boffNN = (uint32_t)((lane & 15) * PBN + (lane >> 4) * 16);

    for (int c = 0; c < NC; ++c) {
        CP_WAIT(STAGES - 2);
        __syncthreads();
        if (c + STAGES - 1 < NC) FILL((c + STAGES - 1) & 3, c + STAGES - 1);
        CP_COMMIT();

        const uint32_t stb   = sb + (c & 3) * SB;
        const uint32_t aBase = stb + (uint32_t)(wm * 64) * PA + aoff;
        const uint32_t bBase = BNN
            ? (stb + ABYTES + (uint32_t)(wn * 32) * 2 + boffNN)
            : (stb + ABYTES + (uint32_t)(wn * 32) * PA + boffNT);

        #pragma unroll
        for (int s = 0; s < 2; ++s) {     // two k16 steps
            uint32_t bf[4][2];
            if (BNN) {
                uint32_t t[4];
                ldsm_x4_t(t, bBase + (uint32_t)(s * 16) * PBN);
                bf[0][0] = t[0]; bf[0][1] = t[1]; bf[1][0] = t[2]; bf[1][1] = t[3];
                ldsm_x4_t(t, bBase + (uint32_t)(s * 16) * PBN + 32);
                bf[2][0] = t[0]; bf[2][1] = t[1]; bf[3][0] = t[2]; bf[3][1] = t[3];
            } else {
                uint32_t t[4];
                ldsm_x4(t, bBase + s * 32);
                bf[0][0] = t[0]; bf[0][1] = t[1]; bf[1][0] = t[2]; bf[1][1] = t[3];
                ldsm_x4(t, bBase + 16 * PA + s * 32);
                bf[2][0] = t[0]; bf[2][1] = t[1]; bf[3][0] = t[2]; bf[3][1] = t[3];
            }
            #pragma unroll
            for (int mt = 0; mt < 4; ++mt) {
                uint32_t af[4];
                ldsm_x4(af, aBase + (uint32_t)(mt * 16) * PA + s * 32);
                #pragma unroll
                for (int nt = 0; nt < 4; ++nt)
                    mma_bf16(acc[mt][nt], af, bf[nt]);
            }
        }
    }

    // ---- epilogue ----
    #pragma unroll
    for (int mt = 0; mt < 4; ++mt) {
        #pragma unroll
        for (int nt = 0; nt < 4; ++nt) {
            const int row = m0 + wm * 64 + mt * 16 + fr;
            const int col = n0 + wn * 32 + nt * 8 + 2 * fc;
            float b0 = 0.f, b1 = 0.f;
            if (HAS_BIAS) { b0 = bias[col]; b1 = bias[col + 1]; }
            float v00 = acc[mt][nt][0] + b0, v01 = acc[mt][nt][1] + b1;
            float v10 = acc[mt][nt][2] + b0, v11 = acc[mt][nt][3] + b1;
            if (RELU) {
                v00 = fmaxf(v00, 0.f); v01 = fmaxf(v01, 0.f);
                v10 = fmaxf(v10, 0.f); v11 = fmaxf(v11, 0.f);
            }
            if constexpr (sizeof(TO) == 4) {
                *(float2*)((float*)C + (size_t)row * ldc + col) = make_float2(v00, v01);
                *(float2*)((float*)C + (size_t)(row + 8) * ldc + col) = make_float2(v10, v11);
            } else {
                __nv_bfloat162 p0, p1;
                p0.x = __float2bfloat16_rn(v00); p0.y = __float2bfloat16_rn(v01);
                p1.x = __float2bfloat16_rn(v10); p1.y = __float2bfloat16_rn(v11);
                *(__nv_bfloat162*)((bf16*)C + (size_t)row * ldc + col) = p0;
                *(__nv_bfloat162*)((bf16*)C + (size_t)(row + 8) * ldc + col) = p1;
            }
        }
    }
    #undef FILL
}

#define SMEM_NT (STAGES * (ABYTES + ABYTES))      // 81920
#define SMEM_NN (STAGES * (ABYTES + 32 * PBN))    // 75776

// ---------------------------------------------------------------------------
__global__ void cvt_bf(const float* __restrict__ in, bf16* __restrict__ out, int n4)
{
    int i = blockIdx.x * 256 + threadIdx.x;
    if (i < n4) {
        float4 v = ((const float4*)in)[i];
        __nv_bfloat162 a, b;
        a.x = __float2bfloat16_rn(v.x); a.y = __float2bfloat16_rn(v.y);
        b.x = __float2bfloat16_rn(v.z); b.y = __float2bfloat16_rn(v.w);
        ((__nv_bfloat162*)out)[2 * i]     = a;
        ((__nv_bfloat162*)out)[2 * i + 1] = b;
    }
}

__global__ void trp_f2b(const float* __restrict__ in, bf16* __restrict__ out,
                        int R, int Cc)
{
    __shared__ float t[32][33];
    const int c0 = blockIdx.x * 32, r0 = blockIdx.y * 32;
    const int x = threadIdx.x, y = threadIdx.y;
    #pragma unroll
    for (int i = 0; i < 32; i += 8)
        t[y + i][x] = in[(size_t)(r0 + y + i) * Cc + c0 + x];
    __syncthreads();
    #pragma unroll
    for (int i = 0; i < 32; i += 8)
        out[(size_t)(c0 + y + i) * R + r0 + x] = __float2bfloat16_rn(t[x][y + i]);
}

// ---------------------------------------------------------------------------
// Single-pass causal softmax: fp32 scores in, bf16 weights out.
// Writes only columns < 128-block end of this row (ctx GEMM never reads beyond).
// ---------------------------------------------------------------------------
__global__ void softmax_causal(const float* __restrict__ Sc, bf16* __restrict__ W)
{
    const int row = blockIdx.x, bb = blockIdx.y;
    const float* r = Sc + (size_t)bb * S_ * S_ + (size_t)row * S_;
    bf16* w = W + (size_t)bb * S_ * S_ + (size_t)row * S_;
    const int n = row + 1;
    const int bend = ((row >> 7) + 1) << 7;     // write limit
    const int tid = threadIdx.x;
    const int lane = tid & 31, warp = tid >> 5;
    __shared__ float red[8];

    float v[8];
    #pragma unroll
    for (int q = 0; q < 8; q++) {
        const int j = tid + q * 256;
        v[q] = (j < n) ? r[j] : -INFINITY;
    }

    float m = v[0];
    #pragma unroll
    for (int q = 1; q < 8; q++) m = fmaxf(m, v[q]);
    #pragma unroll
    for (int s = 16; s > 0; s >>= 1) m = fmaxf(m, __shfl_xor_sync(~0u, m, s));
    if (lane == 0) red[warp] = m;
    __syncthreads();
    m = red[lane & 7];
    #pragma unroll
    for (int s = 4; s > 0; s >>= 1) m = fmaxf(m, __shfl_xor_sync(~0u, m, s));

    float sum = 0.0f;
    #pragma unroll
    for (int q = 0; q < 8; q++) {
        v[q] = (v[q] == -INFINITY) ? 0.0f : __expf(v[q] - m);
        sum += v[q];
    }
    #pragma unroll
    for (int s = 16; s > 0; s >>= 1) sum += __shfl_xor_sync(~0u, sum, s);
    __syncthreads();
    if (lane == 0) red[warp] = sum;
    __syncthreads();
    sum = red[lane & 7];
    #pragma unroll
    for (int s = 4; s > 0; s >>= 1) sum += __shfl_xor_sync(~0u, sum, s);
    const float inv = 1.0f / sum;

    #pragma unroll
    for (int q = 0; q < 8; q++) {
        const int j = tid + q * 256;
        if (j < bend) w[j] = __float2bfloat16_rn(v[q] * inv);
    }
}

// ---------------------------------------------------------------------------
__global__ void head_kernel(const float* __restrict__ O, const float* __restrict__ W4,
                            const float* __restrict__ b4, float* __restrict__ out)
{
    __shared__ float w[DH2 * DOUT];
    const int tid = threadIdx.x;
    for (int i = tid; i < DH2 * DOUT; i += 256) w[i] = W4[i];
    __syncthreads();

    const int warp = tid >> 5, lane = tid & 31;
    const int row = blockIdx.x * 8 + warp;
    const float* o = O + (size_t)row * DH2;

    float acc[DOUT];
    #pragma unroll
    for (int j = 0; j < DOUT; j++) acc[j] = 0.0f;
    for (int k = lane; k < DH2; k += 32) {
        float ov = o[k];
        const float* wk = &w[k * DOUT];
        #pragma unroll
        for (int j = 0; j < DOUT; j++) acc[j] = fmaf(ov, wk[j], acc[j]);
    }
    #pragma unroll
    for (int j = 0; j < DOUT; j++)
        #pragma unroll
        for (int s = 16; s > 0; s >>= 1)
            acc[j] += __shfl_xor_sync(0xffffffffu, acc[j], s);

    if (lane == 0) {
        float m = -INFINITY;
        #pragma unroll
        for (int j = 0; j < DOUT; j++) { acc[j] += b4[j]; m = fmaxf(m, acc[j]); }
        float sum = 0.0f;
        #pragma unroll
        for (int j = 0; j < DOUT; j++) sum += expf(acc[j] - m);
        float lse = m + logf(sum);
        #pragma unroll
        for (int j = 0; j < DOUT; j++)
            out[(size_t)row * DOUT + j] = acc[j] - lse;
    }
}

// ---------------------------------------------------------------------------
extern "C" void kernel_launch(void* const* d_in, const int* in_sizes, int n_in,
                              void* d_out, int out_size)
{
    const float* input = (const float*)d_in[0];
    const float* gamev = (const float*)d_in[1];
    const float* userv = (const float*)d_in[2];
    const float* W1 = (const float*)d_in[3];
    const float* b1 = (const float*)d_in[4];
    const float* W2 = (const float*)d_in[5];
    const float* b2 = (const float*)d_in[6];
    const float* W3 = (const float*)d_in[7];
    const float* b3 = (const float*)d_in[8];
    const float* W4 = (const float*)d_in[9];
    const float* b4 = (const float*)d_in[10];
    float* out = (float*)d_out;

    bf16 *inb, *w1t, *w2t, *w3t, *h1b, *hb, *attnb, *ctxb;
    float *attn, *o;
    cudaGetSymbolAddress((void**)&inb,   g_inb);
    cudaGetSymbolAddress((void**)&w1t,   g_w1t);
    cudaGetSymbolAddress((void**)&w2t,   g_w2t);
    cudaGetSymbolAddress((void**)&w3t,   g_w3t);
    cudaGetSymbolAddress((void**)&h1b,   g_h1b);
    cudaGetSymbolAddress((void**)&hb,    g_hb);
    cudaGetSymbolAddress((void**)&attn,  g_attn);
    cudaGetSymbolAddress((void**)&attnb, g_attnb);
    cudaGetSymbolAddress((void**)&ctxb,  g_ctxb);
    cudaGetSymbolAddress((void**)&o,     g_o);

    //                  TO     RELU  BIAS  BNN    CSKIP  KCUT  REVY
    auto g_mlpB = gemm_bf<bf16,  true,  true,  false, false, false, false>;
    auto g_sc   = gemm_bf<float, false, false, false, true,  false, false>;
    auto g_ctxk = gemm_bf<bf16,  false, false, true,  false, true,  true >;
    auto g_mlpF = gemm_bf<float, true,  true,  false, false, false, false>;
    cudaFuncSetAttribute(g_mlpB, cudaFuncAttributeMaxDynamicSharedMemorySize, SMEM_NT);
    cudaFuncSetAttribute(g_sc,   cudaFuncAttributeMaxDynamicSharedMemorySize, SMEM_NT);
    cudaFuncSetAttribute(g_ctxk, cudaFuncAttributeMaxDynamicSharedMemorySize, SMEM_NN);
    cudaFuncSetAttribute(g_mlpF, cudaFuncAttributeMaxDynamicSharedMemorySize, SMEM_NT);

    // operand conversions
    cvt_bf<<<(M_ * DIN / 4 + 255) / 256, 256>>>(input, inb, M_ * DIN / 4);
    trp_f2b<<<dim3((2*DIN)/32, DIN/32), dim3(32, 8)>>>(W1, w1t, DIN, 2*DIN);
    trp_f2b<<<dim3(DH/32, (2*DIN)/32),  dim3(32, 8)>>>(W2, w2t, 2*DIN, DH);
    trp_f2b<<<dim3(DH2/32, DH/32),      dim3(32, 8)>>>(W3, w3t, DH, DH2);

    // 1) h1 = relu(in @ W1 + b1)    M=32768 N=1024 K=512
    g_mlpB<<<dim3(8, 256, 1), 256, SMEM_NT>>>(inb, w1t, b1, h1b,
        DIN, DIN, 2*DIN, DIN, 0, 0, 0);
    // 2) h = relu(h1 @ W2 + b2)     M=32768 N=1024 K=1024
    g_mlpB<<<dim3(8, 256, 1), 256, SMEM_NT>>>(h1b, w2t, b2, hb,
        2*DIN, 2*DIN, DH, 2*DIN, 0, 0, 0);
    // 3) scores = H @ H^T per batch (lower-tri tiles), fp32 out
    g_sc<<<dim3(16, 16, B_), 256, SMEM_NT>>>(hb, hb, nullptr, attn,
        DH, DH, S_, DH, (size_t)S_*DH, (size_t)S_*DH, (size_t)S_*S_);
    // 4) causal softmax fp32 -> bf16 weights (block-bounded writes)
    softmax_causal<<<dim3(S_, B_), 256>>>(attn, attnb);
    // 5) ctx = attn @ H per batch (NN, K cutoff, LPT order)
    g_ctxk<<<dim3(8, 16, B_), 256, SMEM_NN>>>(attnb, hb, nullptr, ctxb,
        S_, DH, DH, S_, (size_t)S_*S_, (size_t)S_*DH, (size_t)S_*DH);
    // 6) o = relu(ctx @ W3 + b3)    M=32768 N=512 K=1024 -> fp32
    g_mlpF<<<dim3(4, 256, 1), 256, SMEM_NT>>>(ctxb, w3t, b3, o,
        DH, DH, DH2, DH, 0, 0, 0);
    // 7) head + log_softmax
    head_kernel<<<M_ / 8, 256>>>(o, W4, b4, out);

    // 8) pass-through
    size_t off = (size_t)M_ * DOUT;
    cudaMemcpyAsync(out + off, gamev, (size_t)in_sizes[1] * sizeof(float),
                    cudaMemcpyDeviceToDevice);
    cudaMemcpyAsync(out + off + in_sizes[1], userv, (size_t)in_sizes[2] * sizeof(float),
                    cudaMemcpyDeviceToDevice);
}